// round 6
// baseline (speedup 1.0000x reference)
#include <cuda_runtime.h>
#include <cstdint>

#define BB    64
#define TOPK  2
#define EE    16
#define CC    1024
#define KK    4096
#define NTOK  (BB * TOPK)     // 128

#define WARPS  8
#define CTILE  16              // rows per CTA
#define RPW    4               // rows per warp (warps 0-3 == warps 4-7 row-wise)
#define TCH    16              // tokens per chunk (split 8/8 across warp halves)
#define K4     (KK / 4)        // 1024 float4 per row
#define JITERS (K4 / 32)       // 32 k-steps (512B per row per step)
#define NSTAGE 5

// one stage = 16 w-rows + 16 a-rows, each 32 float4 (512B)
#define ST_F4     (32 * 32)                  // 1024 float4 = 16KB
#define DYN_BYTES (NSTAGE * ST_F4 * 16)      // 81920

__device__ float g_tmp[NTOK * CC];

// ---- PTX helpers -----------------------------------------------------------
__device__ __forceinline__ void cp16(uint32_t dst, const void* src) {
    asm volatile("cp.async.cg.shared.global [%0], [%1], 16;"
                 :: "r"(dst), "l"(src) : "memory");
}
__device__ __forceinline__ void cp_commit() {
    asm volatile("cp.async.commit_group;" ::: "memory");
}
template <int N>
__device__ __forceinline__ void cp_wait() {
    asm volatile("cp.async.wait_group %0;" :: "n"(N) : "memory");
}
__device__ __forceinline__ void ffma2(unsigned long long& acc,
                                      unsigned long long w,
                                      unsigned long long a) {
    asm("fma.rn.f32x2 %0, %1, %2, %0;" : "+l"(acc) : "l"(w), "l"(a));
}
__device__ __forceinline__ float pair_sum(unsigned long long p) {
    float lo, hi;
    asm("mov.b64 {%0, %1}, %2;" : "=f"(lo), "=f"(hi) : "l"(p));
    return lo + hi;
}

// ---------------------------------------------------------------------------
// Grouped expert matvec. Grid (CC/CTILE=64, EE=16). Block 256 (8 warps), occ 2.
// Stage: [16 w rows | 16 a rows] x 512B. 5-stage cp.async pipeline.
// Fill: thread(warp,lane) stages w rows {warp, warp+8} + a tokens {warp, warp+8}.
// Consume: warp (wg=warp/4, wr=warp%4) -> rows wr*4..+3, tokens wg*8..+7.
// Token split across warp halves cuts smem a-duplication 8x -> 4x.
// ---------------------------------------------------------------------------
__global__ void __launch_bounds__(256, 2)
matvec(const float* __restrict__ act,
       const float* __restrict__ W,
       const int*  __restrict__ eidx) {
    extern __shared__ float4 st[];           // [NSTAGE][32][32] float4

    __shared__ int se[NTOK];
    __shared__ int stok[NTOK];

    const int tid = threadIdx.x;
    const int e   = blockIdx.y;

    if (tid < NTOK) se[tid] = eidx[tid];
    __syncthreads();
    int mine = (tid < NTOK) && (se[tid] == e);
    if (mine) {
        int pos = 0;
        for (int j = 0; j < tid; ++j) pos += (se[j] == e) ? 1 : 0;
        stok[pos] = tid;
    }
    const int cnt = __syncthreads_count(mine);
    if (cnt == 0) return;

    const int warp = tid >> 5;
    const int lane = tid & 31;
    const int c0   = blockIdx.x * CTILE;
    const int wg   = warp >> 2;              // token half
    const int wr   = warp & 3;               // row quad

    // fill sources: w rows (warp, warp+8) of this CTA's tile, lane column
    const float4* __restrict__ w0 =
        reinterpret_cast<const float4*>(W) + ((size_t)(e * CC + c0 + warp)) * K4 + lane;
    const float4* __restrict__ w1 = w0 + (size_t)8 * K4;
    const uint32_t dst0 =
        (uint32_t)__cvta_generic_to_shared(&st[(size_t)warp * 32 + lane]);

    for (int t0 = 0; t0 < cnt; t0 += TCH) {
        // fill sources: a tokens (t0+warp, t0+8+warp), clamped on tail
        int ta0 = t0 + warp;      if (ta0 >= cnt) ta0 = cnt - 1;
        int ta1 = t0 + 8 + warp;  if (ta1 >= cnt) ta1 = cnt - 1;
        const float4* a0 =
            reinterpret_cast<const float4*>(act) + (size_t)stok[ta0] * K4 + lane;
        const float4* a1 =
            reinterpret_cast<const float4*>(act) + (size_t)stok[ta1] * K4 + lane;

        unsigned long long acc[RPW][8];
#pragma unroll
        for (int r = 0; r < RPW; ++r)
#pragma unroll
            for (int t = 0; t < 8; ++t) acc[r][t] = 0ull;

        // ---- prime stages 0 .. NSTAGE-2 ----
#pragma unroll
        for (int s = 0; s < NSTAGE - 1; ++s) {
            const uint32_t d = dst0 + s * (ST_F4 * 16);
            cp16(d,              w0 + s * 32);
            cp16(d + 8  * 512,   w1 + s * 32);   // row warp+8
            cp16(d + 16 * 512,   a0 + s * 32);   // a token warp
            cp16(d + 24 * 512,   a1 + s * 32);   // a token warp+8
            cp_commit();
        }

#pragma unroll 1
        for (int j = 0; j < JITERS; ++j) {
            cp_wait<NSTAGE - 2>();
            __syncthreads();

            const int jf = j + NSTAGE - 1;
            if (jf < JITERS) {
                const int sf = jf % NSTAGE;
                const uint32_t d = dst0 + sf * (ST_F4 * 16);
                cp16(d,            w0 + jf * 32);
                cp16(d + 8  * 512, w1 + jf * 32);
                cp16(d + 16 * 512, a0 + jf * 32);
                cp16(d + 24 * 512, a1 + jf * 32);
            }
            cp_commit();                     // keep group counts aligned

            // ---- consume stage j%NSTAGE ----
            const ulonglong2* base =
                reinterpret_cast<const ulonglong2*>(st + (size_t)(j % NSTAGE) * ST_F4);
            const ulonglong2* wb = base + (wr * RPW) * 32 + lane;
            const ulonglong2* ab = base + (16 + wg * 8) * 32 + lane;

            ulonglong2 wv[RPW];
#pragma unroll
            for (int r = 0; r < RPW; ++r) wv[r] = wb[r * 32];
#pragma unroll
            for (int t = 0; t < 8; ++t) {
                ulonglong2 av = ab[t * 32];
#pragma unroll
                for (int r = 0; r < RPW; ++r) {
                    ffma2(acc[r][t], wv[r].x, av.x);
                    ffma2(acc[r][t], wv[r].y, av.y);
                }
            }
        }

        // ---- fold, warp-reduce, store ----
#pragma unroll
        for (int r = 0; r < RPW; ++r) {
#pragma unroll
            for (int t = 0; t < 8; ++t) {
                float v = pair_sum(acc[r][t]);
                v += __shfl_xor_sync(0xFFFFFFFFu, v, 16);
                v += __shfl_xor_sync(0xFFFFFFFFu, v, 8);
                v += __shfl_xor_sync(0xFFFFFFFFu, v, 4);
                v += __shfl_xor_sync(0xFFFFFFFFu, v, 2);
                v += __shfl_xor_sync(0xFFFFFFFFu, v, 1);
                const int slot = t0 + wg * 8 + t;
                if (lane == 0 && slot < cnt)
                    g_tmp[stok[slot] * CC + c0 + wr * RPW + r] = v;
            }
        }
        __syncthreads();   // all stage reads done before next chunk re-primes
    }
}

// ---------------------------------------------------------------------------
__global__ void finalize(const float* __restrict__ residual,
                         const float* __restrict__ bias,
                         const float* __restrict__ ew,
                         const int*  __restrict__ eidx,
                         float* __restrict__ out) {
    const int idx = blockIdx.x * blockDim.x + threadIdx.x;   // over BB*CC/4
    const int b   = idx / (CC / 4);
    const int c4  = idx % (CC / 4);

    const float4* r4 = reinterpret_cast<const float4*>(residual);
    const float4* b4 = reinterpret_cast<const float4*>(bias);
    const float4* t4 = reinterpret_cast<const float4*>(g_tmp);
    float4 v = r4[b * (CC / 4) + c4];
#pragma unroll
    for (int s = 0; s < TOPK; ++s) {
        const int   e = eidx[b * TOPK + s];
        const float w = ew[b * TOPK + s];
        float4 t  = t4[(b * TOPK + s) * (CC / 4) + c4];
        float4 bb = b4[e * (CC / 4) + c4];
        v.x += w * (t.x + bb.x);
        v.y += w * (t.y + bb.y);
        v.z += w * (t.z + bb.z);
        v.w += w * (t.w + bb.w);
    }
    reinterpret_cast<float4*>(out)[b * (CC / 4) + c4] = v;
}

__global__ void epilogue_nop() {}

// ---------------------------------------------------------------------------
extern "C" void kernel_launch(void* const* d_in, const int* in_sizes, int n_in,
                              void* d_out, int out_size) {
    const float* activated      = (const float*)d_in[0];
    const int*   expert_indices = (const int*)  d_in[1];
    const float* expert_weights = (const float*)d_in[2];
    const float* mlp2_weight    = (const float*)d_in[3];
    const float* mlp2_bias      = (const float*)d_in[4];
    const float* residual_x     = (const float*)d_in[5];
    float*       out            = (float*)d_out;

    static bool attr_done = false;
    if (!attr_done) {
        cudaFuncSetAttribute(matvec, cudaFuncAttributeMaxDynamicSharedMemorySize,
                             DYN_BYTES);
        attr_done = true;
    }

    dim3 grid(CC / CTILE, EE);
    matvec<<<grid, WARPS * 32, DYN_BYTES>>>(activated, mlp2_weight,
                                            expert_indices);

    finalize<<<(BB * CC / 4) / 256, 256>>>(residual_x, mlp2_bias,
                                           expert_weights, expert_indices, out);
    epilogue_nop<<<1, 1>>>();
}